// round 1
// baseline (speedup 1.0000x reference)
#include <cuda_runtime.h>
#include <mma.h>
#include <math.h>

using namespace nvcuda;

#define BATCH 2048
#define HID   1024
#define FFN   4096
#define NEXP  8
#define TOPK  2

#define BM 64
#define BN 128
#define BK 32

// ---------------- device scratch (no allocations allowed) ----------------
__device__ int   g_cnt[NEXP];
__device__ int   g_tok[NEXP][BATCH];
__device__ int   g_slot[NEXP][BATCH];
__device__ float g_wgt[NEXP][BATCH];
__device__ float g_h[BATCH * TOPK][FFN];   // 64 MB silu(x@w1) scratch
__device__ int   g_is64;

// ---------------- zero out + counters ----------------
__global__ void k_zero(float* __restrict__ out) {
    int i = blockIdx.x * blockDim.x + threadIdx.x;
    if (i < (BATCH * HID) / 4) {
        ((float4*)out)[i] = make_float4(0.f, 0.f, 0.f, 0.f);
    }
    if (i < NEXP) g_cnt[i] = 0;
}

// ---------------- detect int64 vs int32 expert_indices ----------------
__global__ void k_detect(const long long* __restrict__ idx64) {
    __shared__ int bad;
    if (threadIdx.x == 0) bad = 0;
    __syncthreads();
    for (int i = threadIdx.x; i < BATCH * TOPK; i += blockDim.x) {
        long long v = idx64[i];
        if (v < 0 || v >= NEXP) bad = 1;
    }
    __syncthreads();
    if (threadIdx.x == 0) g_is64 = (bad == 0) ? 1 : 0;
}

// ---------------- routing: build per-expert entry lists ----------------
__global__ void k_route(const void* __restrict__ idx_raw,
                        const float* __restrict__ rw) {
    int b = blockIdx.x * blockDim.x + threadIdx.x;
    if (b >= BATCH) return;
    const long long* i64 = (const long long*)idx_raw;
    const int*       i32 = (const int*)idx_raw;
    int use64 = g_is64;
    int e0 = use64 ? (int)i64[2 * b]     : i32[2 * b];
    int e1 = use64 ? (int)i64[2 * b + 1] : i32[2 * b + 1];
    float r0 = rw[2 * b];
    float r1 = rw[2 * b + 1];
    if (e0 == e1) {
        int p = atomicAdd(&g_cnt[e0], 1);
        g_tok[e0][p]  = b;
        g_slot[e0][p] = 2 * b;
        g_wgt[e0][p]  = r0 + r1;
    } else {
        int p = atomicAdd(&g_cnt[e0], 1);
        g_tok[e0][p]  = b;
        g_slot[e0][p] = 2 * b;
        g_wgt[e0][p]  = r0;
        p = atomicAdd(&g_cnt[e1], 1);
        g_tok[e1][p]  = b;
        g_slot[e1][p] = 2 * b + 1;
        g_wgt[e1][p]  = r1;
    }
}

// ---------------- shared mem tile union ----------------
struct __align__(16) SmemAB {
    float A[BM][BK + 4];   // 64 x 36
    float B[BK][BN + 4];   // 32 x 132
};
union __align__(16) SmemT {
    SmemAB ab;
    float  C[BM][BN + 4];  // 64 x 132
};

typedef wmma::fragment<wmma::matrix_a, 16, 16, 8, wmma::precision::tf32, wmma::row_major> FragA;
typedef wmma::fragment<wmma::matrix_b, 16, 16, 8, wmma::precision::tf32, wmma::row_major> FragB;
typedef wmma::fragment<wmma::accumulator, 16, 16, 8, float> FragC;

// ---------------- GEMM1: H[slot] = silu(X[tok] @ W1[e]) ----------------
__global__ void __launch_bounds__(256) k_gemm1(const float* __restrict__ x,
                                               const float* __restrict__ w1) {
    int e  = blockIdx.z;
    int ne = g_cnt[e];
    int row0 = blockIdx.y * BM;
    if (row0 >= ne) return;
    int n0 = blockIdx.x * BN;

    __shared__ SmemT sm;
    __shared__ int s_tok[BM];
    __shared__ int s_slot[BM];

    int tid = threadIdx.x;
    if (tid < BM) {
        int r = row0 + tid;
        s_tok[tid]  = (r < ne) ? g_tok[e][r]  : -1;
        s_slot[tid] = (r < ne) ? g_slot[e][r] : -1;
    }
    __syncthreads();

    FragC acc[2][2];
    #pragma unroll
    for (int i = 0; i < 2; i++)
        #pragma unroll
        for (int j = 0; j < 2; j++)
            wmma::fill_fragment(acc[i][j], 0.f);

    int warp = tid >> 5;
    int wm = (warp >> 2) * 32;   // 0 or 32
    int wn = (warp & 3) * 32;    // 0..96

    for (int k0 = 0; k0 < HID; k0 += BK) {
        // A tile: 64x32 gathered rows from x
        #pragma unroll
        for (int i = 0; i < 2; i++) {
            int li = tid + i * 256;          // 0..511
            int r  = li >> 3;
            int c4 = li & 7;
            int t  = s_tok[r];
            float4 v = (t >= 0)
                ? *(const float4*)&x[(size_t)t * HID + k0 + c4 * 4]
                : make_float4(0.f, 0.f, 0.f, 0.f);
            *(float4*)&sm.ab.A[r][c4 * 4] = v;
        }
        // B tile: 32x128 from w1[e][k0+r][n0+c]
        const float* bsrc = w1 + ((size_t)e * HID + k0) * FFN + n0;
        #pragma unroll
        for (int i = 0; i < 4; i++) {
            int li = tid + i * 256;          // 0..1023
            int r  = li >> 5;
            int c4 = li & 31;
            float4 v = *(const float4*)&bsrc[(size_t)r * FFN + c4 * 4];
            *(float4*)&sm.ab.B[r][c4 * 4] = v;
        }
        __syncthreads();

        #pragma unroll
        for (int kk = 0; kk < BK; kk += 8) {
            FragA a[2];
            FragB b[2];
            #pragma unroll
            for (int i = 0; i < 2; i++) {
                wmma::load_matrix_sync(a[i], &sm.ab.A[wm + i * 16][kk], BK + 4);
                #pragma unroll
                for (int t = 0; t < a[i].num_elements; t++)
                    a[i].x[t] = wmma::__float_to_tf32(a[i].x[t]);
            }
            #pragma unroll
            for (int j = 0; j < 2; j++) {
                wmma::load_matrix_sync(b[j], &sm.ab.B[kk][wn + j * 16], BN + 4);
                #pragma unroll
                for (int t = 0; t < b[j].num_elements; t++)
                    b[j].x[t] = wmma::__float_to_tf32(b[j].x[t]);
            }
            #pragma unroll
            for (int i = 0; i < 2; i++)
                #pragma unroll
                for (int j = 0; j < 2; j++)
                    wmma::mma_sync(acc[i][j], a[i], b[j], acc[i][j]);
        }
        __syncthreads();
    }

    // silu then stage to shared C
    #pragma unroll
    for (int i = 0; i < 2; i++)
        #pragma unroll
        for (int j = 0; j < 2; j++) {
            #pragma unroll
            for (int t = 0; t < acc[i][j].num_elements; t++) {
                float v = acc[i][j].x[t];
                acc[i][j].x[t] = v / (1.f + __expf(-v));
            }
            wmma::store_matrix_sync(&sm.C[wm + i * 16][wn + j * 16], acc[i][j],
                                    BN + 4, wmma::mem_row_major);
        }
    __syncthreads();

    // scatter rows to g_h[slot]
    #pragma unroll
    for (int i = 0; i < 8; i++) {
        int li = tid + i * 256;              // 0..2047
        int r  = li >> 5;
        int c4 = li & 31;
        int sl = s_slot[r];
        if (sl >= 0)
            *(float4*)&g_h[sl][n0 + c4 * 4] = *(float4*)&sm.C[r][c4 * 4];
    }
}

// ---------------- GEMM2: out[tok] += w * (H[slot] @ W2[e]) ----------------
__global__ void __launch_bounds__(256) k_gemm2(const float* __restrict__ w2,
                                               float* __restrict__ out) {
    int e  = blockIdx.z;
    int ne = g_cnt[e];
    int row0 = blockIdx.y * BM;
    if (row0 >= ne) return;
    int n0 = blockIdx.x * BN;

    __shared__ SmemT sm;
    __shared__ int   s_tok[BM];
    __shared__ int   s_slot[BM];
    __shared__ float s_w[BM];

    int tid = threadIdx.x;
    if (tid < BM) {
        int r = row0 + tid;
        s_tok[tid]  = (r < ne) ? g_tok[e][r]  : -1;
        s_slot[tid] = (r < ne) ? g_slot[e][r] : -1;
        s_w[tid]    = (r < ne) ? g_wgt[e][r]  : 0.f;
    }
    __syncthreads();

    FragC acc[2][2];
    #pragma unroll
    for (int i = 0; i < 2; i++)
        #pragma unroll
        for (int j = 0; j < 2; j++)
            wmma::fill_fragment(acc[i][j], 0.f);

    int warp = tid >> 5;
    int wm = (warp >> 2) * 32;
    int wn = (warp & 3) * 32;

    for (int k0 = 0; k0 < FFN; k0 += BK) {
        // A tile: 64x32 gathered rows from g_h
        #pragma unroll
        for (int i = 0; i < 2; i++) {
            int li = tid + i * 256;
            int r  = li >> 3;
            int c4 = li & 7;
            int sl = s_slot[r];
            float4 v = (sl >= 0)
                ? *(const float4*)&g_h[sl][k0 + c4 * 4]
                : make_float4(0.f, 0.f, 0.f, 0.f);
            *(float4*)&sm.ab.A[r][c4 * 4] = v;
        }
        // B tile: 32x128 from w2[e][k0+r][n0+c]
        const float* bsrc = w2 + ((size_t)e * FFN + k0) * HID + n0;
        #pragma unroll
        for (int i = 0; i < 4; i++) {
            int li = tid + i * 256;
            int r  = li >> 5;
            int c4 = li & 31;
            float4 v = *(const float4*)&bsrc[(size_t)r * HID + c4 * 4];
            *(float4*)&sm.ab.B[r][c4 * 4] = v;
        }
        __syncthreads();

        #pragma unroll
        for (int kk = 0; kk < BK; kk += 8) {
            FragA a[2];
            FragB b[2];
            #pragma unroll
            for (int i = 0; i < 2; i++) {
                wmma::load_matrix_sync(a[i], &sm.ab.A[wm + i * 16][kk], BK + 4);
                #pragma unroll
                for (int t = 0; t < a[i].num_elements; t++)
                    a[i].x[t] = wmma::__float_to_tf32(a[i].x[t]);
            }
            #pragma unroll
            for (int j = 0; j < 2; j++) {
                wmma::load_matrix_sync(b[j], &sm.ab.B[kk][wn + j * 16], BN + 4);
                #pragma unroll
                for (int t = 0; t < b[j].num_elements; t++)
                    b[j].x[t] = wmma::__float_to_tf32(b[j].x[t]);
            }
            #pragma unroll
            for (int i = 0; i < 2; i++)
                #pragma unroll
                for (int j = 0; j < 2; j++)
                    wmma::mma_sync(acc[i][j], a[i], b[j], acc[i][j]);
        }
        __syncthreads();
    }

    // stage to shared C
    #pragma unroll
    for (int i = 0; i < 2; i++)
        #pragma unroll
        for (int j = 0; j < 2; j++)
            wmma::store_matrix_sync(&sm.C[wm + i * 16][wn + j * 16], acc[i][j],
                                    BN + 4, wmma::mem_row_major);
    __syncthreads();

    // weighted atomic scatter-combine into out
    #pragma unroll
    for (int i = 0; i < 8; i++) {
        int li = tid + i * 256;
        int r  = li >> 5;
        int c4 = li & 31;
        int t  = s_tok[r];
        if (t >= 0) {
            float w = s_w[r];
            float4 v = *(const float4*)&sm.C[r][c4 * 4];
            float* dst = &out[(size_t)t * HID + n0 + c4 * 4];
            atomicAdd(dst + 0, w * v.x);
            atomicAdd(dst + 1, w * v.y);
            atomicAdd(dst + 2, w * v.z);
            atomicAdd(dst + 3, w * v.w);
        }
    }
}

// ---------------- launch ----------------
extern "C" void kernel_launch(void* const* d_in, const int* in_sizes, int n_in,
                              void* d_out, int out_size) {
    const float* x   = (const float*)d_in[0];   // [2048,1024]
    const float* rw  = (const float*)d_in[1];   // [2048,2]
    const float* w1  = (const float*)d_in[2];   // [8,1024,4096]
    const float* w2  = (const float*)d_in[3];   // [8,4096,1024]
    const void*  idx = d_in[4];                 // [2048,2] int64 or int32
    float* out = (float*)d_out;

    k_zero<<<(BATCH * HID / 4 + 255) / 256, 256>>>(out);
    k_detect<<<1, 256>>>((const long long*)idx);
    k_route<<<(BATCH + 255) / 256, 256>>>(idx, rw);

    dim3 g1(FFN / BN, (BATCH + BM - 1) / BM, NEXP);  // (32,32,8)
    k_gemm1<<<g1, 256>>>(x, w1);

    dim3 g2(HID / BN, (BATCH + BM - 1) / BM, NEXP);  // (8,32,8)
    k_gemm2<<<g2, 256>>>(w2, out);
}

// round 5
// speedup vs baseline: 1.0668x; 1.0668x over previous
#include <cuda_runtime.h>
#include <mma.h>
#include <cstdint>

using namespace nvcuda;

#define BATCH 2048
#define HID   1024
#define FFN   4096
#define NEXP  8

#define BM 256
#define BN 128
#define BK 32
#define NTHR 512

// ---------------- device scratch ----------------
__device__ int   g_cnt[NEXP];
__device__ int   g_off[NEXP];          // BM-aligned cumulative offsets
__device__ int   g_tok[NEXP][BATCH];
__device__ float g_wgt[NEXP][BATCH];
__device__ int   g_inv[BATCH * 2];     // (e<<16)|pos, or -1
__device__ __align__(16) float g_h[6144ull * FFN];   // 100 MB compacted silu(x@w1)
__device__ __align__(16) float g_y[6144ull * HID];   // 25 MB  compacted h@w2
__device__ int   g_is64;

__device__ __forceinline__ uint32_t f2tf32(float f) {
    uint32_t r;
    asm("cvt.rna.tf32.f32 %0, %1;" : "=r"(r) : "f"(f));
    return r;
}
__device__ __forceinline__ float tf(float f) { return __uint_as_float(f2tf32(f)); }

// ---------------- small kernels ----------------
__global__ void k_zero() {
    if (threadIdx.x < NEXP) g_cnt[threadIdx.x] = 0;
}

__global__ void k_detect(const long long* __restrict__ idx64) {
    __shared__ int bad;
    if (threadIdx.x == 0) bad = 0;
    __syncthreads();
    for (int i = threadIdx.x; i < BATCH * 2; i += blockDim.x) {
        long long v = idx64[i];
        if (v < 0 || v >= NEXP) bad = 1;
    }
    __syncthreads();
    if (threadIdx.x == 0) g_is64 = (bad == 0) ? 1 : 0;
}

__global__ void k_route(const void* __restrict__ idx_raw, const float* __restrict__ rw) {
    int b = blockIdx.x * blockDim.x + threadIdx.x;
    if (b >= BATCH) return;
    const long long* i64 = (const long long*)idx_raw;
    const int* i32 = (const int*)idx_raw;
    int use64 = g_is64;
    int e0 = use64 ? (int)i64[2 * b] : i32[2 * b];
    int e1 = use64 ? (int)i64[2 * b + 1] : i32[2 * b + 1];
    float r0 = rw[2 * b], r1 = rw[2 * b + 1];
    if (e0 == e1) {
        int p = atomicAdd(&g_cnt[e0], 1);
        g_tok[e0][p] = b; g_wgt[e0][p] = r0 + r1;
        g_inv[2 * b] = (e0 << 16) | p;
        g_inv[2 * b + 1] = -1;
    } else {
        int p = atomicAdd(&g_cnt[e0], 1);
        g_tok[e0][p] = b; g_wgt[e0][p] = r0;
        g_inv[2 * b] = (e0 << 16) | p;
        p = atomicAdd(&g_cnt[e1], 1);
        g_tok[e1][p] = b; g_wgt[e1][p] = r1;
        g_inv[2 * b + 1] = (e1 << 16) | p;
    }
}

__global__ void k_scan() {
    int s = 0;
    for (int e = 0; e < NEXP; e++) {
        g_off[e] = s;
        s += (g_cnt[e] + BM - 1) & ~(BM - 1);
    }
}

// combine: out[b] = sum_k wgt_k * g_y[slot_k]
__global__ void __launch_bounds__(256) k_combine(float* __restrict__ out) {
    int b = blockIdx.x;
    int c = threadIdx.x * 4;
    int iv0 = g_inv[2 * b];
    int iv1 = g_inv[2 * b + 1];
    int e0 = iv0 >> 16, p0 = iv0 & 0xFFFF;
    float w0 = g_wgt[e0][p0];
    size_t s0 = (size_t)(g_off[e0] + p0) * HID + c;
    float4 y0 = *(const float4*)&g_y[s0];
    float4 r;
    r.x = w0 * y0.x; r.y = w0 * y0.y; r.z = w0 * y0.z; r.w = w0 * y0.w;
    if (iv1 >= 0) {
        int e1 = iv1 >> 16, p1 = iv1 & 0xFFFF;
        float w1 = g_wgt[e1][p1];
        size_t s1 = (size_t)(g_off[e1] + p1) * HID + c;
        float4 y1 = *(const float4*)&g_y[s1];
        r.x += w1 * y1.x; r.y += w1 * y1.y; r.z += w1 * y1.z; r.w += w1 * y1.w;
    }
    *(float4*)&out[(size_t)b * HID + c] = r;
}

// ---------------- grouped GEMM (wmma tf32, double-buffered) ----------------
// G1: g_h[slot] = silu(X[gather] @ W1[e])   KD=HID, ND=FFN
// G2: g_y[slot] = g_h[slot] @ W2[e]         KD=FFN, ND=HID
typedef wmma::fragment<wmma::matrix_a, 16, 16, 8, wmma::precision::tf32, wmma::row_major> FragA;
typedef wmma::fragment<wmma::matrix_b, 16, 16, 8, wmma::precision::tf32, wmma::row_major> FragB;
typedef wmma::fragment<wmma::accumulator, 16, 16, 8, float> FragC;

// smem float offsets
#define A_STRIDE 40              // 32 + 8 pad
#define B_STRIDE 136             // 128 + 8 pad
#define A_STAGE  (BM * A_STRIDE)         // 10240 floats
#define B_STAGE  (BK * B_STRIDE)         // 4352 floats
#define B_BASE   (2 * A_STAGE)           // 20480
#define SMEM_FLOATS (2 * A_STAGE + 2 * B_STAGE)   // 29184 floats = 116736 B

template<int KD, bool G1>
__global__ void __launch_bounds__(NTHR) k_moe(const float* __restrict__ x,
                                              const float* __restrict__ w) {
    constexpr int ND = G1 ? FFN : HID;
    constexpr int T  = KD / BK;

    const int e    = blockIdx.z;
    const int ne   = g_cnt[e];
    const int row0 = blockIdx.y * BM;
    if (row0 >= ne) return;
    const int n0     = blockIdx.x * BN;
    const int base_e = g_off[e];

    extern __shared__ float sm[];
    __shared__ int s_tok[BM];

    const int tid = threadIdx.x;
    const int wid = tid >> 5;

    if (G1 && tid < BM) {
        int r = row0 + tid;
        s_tok[tid] = (r < ne) ? g_tok[e][r] : -1;
    }
    if (G1) __syncthreads();

    // warp tile: 64 rows x 32 cols; warps 4x4 over 256x128
    const int wm = (wid >> 2) * 64;
    const int wn = (wid & 3) * 32;

    FragC acc[4][2];
    #pragma unroll
    for (int i = 0; i < 4; i++)
        #pragma unroll
        for (int j = 0; j < 2; j++)
            wmma::fill_fragment(acc[i][j], 0.f);

    // per-thread staging: A 4 float4, B 2 float4
    float4 ra[4], rb[2];
    const int ar = tid >> 3;            // A: 512 thr cover 64 rows x 8 f4; 4 iters
    const int ac4 = tid & 7;
    const int bk_ = tid >> 5;           // B: 512 thr cover 16 k x 32 f4; 2 iters
    const int bc4 = tid & 31;

    auto ldg_stage = [&](int t) {
        const int kofs = t * BK;
        #pragma unroll
        for (int i = 0; i < 4; i++) {
            int r = ar + i * 64;
            if (G1) {
                int tk = s_tok[r];
                ra[i] = (tk >= 0) ? *(const float4*)&x[(size_t)tk * KD + kofs + ac4 * 4]
                                  : make_float4(0.f, 0.f, 0.f, 0.f);
            } else {
                ra[i] = *(const float4*)&g_h[(size_t)(base_e + row0 + r) * KD + kofs + ac4 * 4];
            }
        }
        #pragma unroll
        for (int i = 0; i < 2; i++) {
            int k = bk_ + i * 16;
            rb[i] = *(const float4*)&w[((size_t)e * KD + kofs + k) * ND + n0 + bc4 * 4];
        }
    };
    auto sts_stage = [&](int buf) {
        #pragma unroll
        for (int i = 0; i < 4; i++) {
            int r = ar + i * 64;
            float* p = &sm[buf * A_STAGE + r * A_STRIDE + ac4 * 4];
            *(float4*)p = make_float4(tf(ra[i].x), tf(ra[i].y), tf(ra[i].z), tf(ra[i].w));
        }
        #pragma unroll
        for (int i = 0; i < 2; i++) {
            int k = bk_ + i * 16;
            float* p = &sm[B_BASE + buf * B_STAGE + k * B_STRIDE + bc4 * 4];
            *(float4*)p = make_float4(tf(rb[i].x), tf(rb[i].y), tf(rb[i].z), tf(rb[i].w));
        }
    };

    ldg_stage(0);
    sts_stage(0);
    __syncthreads();

    for (int t = 0; t < T; t++) {
        const int buf = t & 1;
        if (t + 1 < T) ldg_stage(t + 1);

        const float* As = &sm[buf * A_STAGE];
        const float* Bs = &sm[B_BASE + buf * B_STAGE];
        #pragma unroll
        for (int kk = 0; kk < BK; kk += 8) {
            FragA a[4];
            FragB b[2];
            #pragma unroll
            for (int i = 0; i < 4; i++)
                wmma::load_matrix_sync(a[i], As + (wm + i * 16) * A_STRIDE + kk, A_STRIDE);
            #pragma unroll
            for (int j = 0; j < 2; j++)
                wmma::load_matrix_sync(b[j], Bs + kk * B_STRIDE + wn + j * 16, B_STRIDE);
            #pragma unroll
            for (int i = 0; i < 4; i++)
                #pragma unroll
                for (int j = 0; j < 2; j++)
                    wmma::mma_sync(acc[i][j], a[i], b[j], acc[i][j]);
        }

        if (t + 1 < T) sts_stage(buf ^ 1);
        __syncthreads();
    }

    // epilogue: straight store_matrix_sync to compact global rows (no atomics)
    float* dst = G1 ? g_h : g_y;
    const size_t grow0 = (size_t)base_e + row0;
    #pragma unroll
    for (int i = 0; i < 4; i++) {
        #pragma unroll
        for (int j = 0; j < 2; j++) {
            if (G1) {
                #pragma unroll
                for (int t = 0; t < acc[i][j].num_elements; t++) {
                    float v = acc[i][j].x[t];
                    acc[i][j].x[t] = v / (1.f + __expf(-v));
                }
            }
            wmma::store_matrix_sync(
                &dst[(grow0 + wm + i * 16) * ND + n0 + wn + j * 16],
                acc[i][j], ND, wmma::mem_row_major);
        }
    }
}

// ---------------- launch ----------------
extern "C" void kernel_launch(void* const* d_in, const int* in_sizes, int n_in,
                              void* d_out, int out_size) {
    const float* x   = (const float*)d_in[0];   // [2048,1024]
    const float* rw  = (const float*)d_in[1];   // [2048,2]
    const float* w1  = (const float*)d_in[2];   // [8,1024,4096]
    const float* w2  = (const float*)d_in[3];   // [8,4096,1024]
    const void*  idx = d_in[4];                 // [2048,2] int64/int32
    float* out = (float*)d_out;

    const int SMEM_BYTES = SMEM_FLOATS * 4;     // 116736

    cudaFuncSetAttribute((const void*)k_moe<HID, true>,
                         cudaFuncAttributeMaxDynamicSharedMemorySize, SMEM_BYTES);
    cudaFuncSetAttribute((const void*)k_moe<FFN, false>,
                         cudaFuncAttributeMaxDynamicSharedMemorySize, SMEM_BYTES);

    k_zero<<<1, 32>>>();
    k_detect<<<1, 256>>>((const long long*)idx);
    k_route<<<(BATCH + 255) / 256, 256>>>(idx, rw);
    k_scan<<<1, 1>>>();

    dim3 g1(FFN / BN, BATCH / BM, NEXP);        // (32, 8, 8)
    k_moe<HID, true><<<g1, NTHR, SMEM_BYTES>>>(x, w1);

    dim3 g2(HID / BN, BATCH / BM, NEXP);        // (8, 8, 8)
    k_moe<FFN, false><<<g2, NTHR, SMEM_BYTES>>>(nullptr, w2);

    k_combine<<<BATCH, 256>>>(out);
}